// round 2
// baseline (speedup 1.0000x reference)
#include <cuda_runtime.h>
#include <cuda_bf16.h>
#include <cstdint>
#include <cstdio>

// Problem constants
#define BB 32
#define CC 512
#define DD 512
#define HH 8
#define WW 64
#define MM (BB*CC)          // 16384 rows
#define NELEM (MM*DD)       // 8388608

// ---------------- device scratch (no allocations allowed) ----------------
__device__ float  g_conv2[NELEM];
__device__ float  g_q[NELEM];          // also reused as greal
__device__ float  g_k[NELEM];          // also reused as gmid
__device__ float  g_v[NELEM];
__device__ float2 g_qf[NELEM];         // reused as gtep after attention
__device__ float2 g_kf[NELEM];
__device__ float2 g_vf[NELEM];
__device__ float2 g_tep[NELEM];
__device__ float  g_cat[MM*1024];      // [16384, 1024] concat buffer

// ---------------- generic shared-memory radix-2 FFT ----------------
// nfft independent FFTs of length N (power of 2). Element i of fft f lives at
// s[f*fstride + i*istride]. dir = -1 forward, +1 inverse. scale applied at end.
__device__ __forceinline__ void fftN(float2* s, int N, int logN, int nfft,
                                     int fstride, int istride,
                                     int tid, int nthreads,
                                     float dir, float scale)
{
    const int total = nfft * N;
    // bit-reverse permutation
    for (int j = tid; j < total; j += nthreads) {
        int f = j % nfft, i = j / nfft;
        int r = (int)(__brev((unsigned)i) >> (32 - logN));
        if (r > i) {
            float2* p0 = &s[f*fstride + i*istride];
            float2* p1 = &s[f*fstride + r*istride];
            float2 t = *p0; *p0 = *p1; *p1 = t;
        }
    }
    __syncthreads();
    for (int half = 1; half < N; half <<= 1) {
        const int nb = nfft * (N >> 1);
        const float angstep = dir * 3.14159265358979323846f / (float)half;
        for (int j = tid; j < nb; j += nthreads) {
            int f = j % nfft, k = j / nfft;
            int pos = k & (half - 1);
            int i0 = 2*k - pos;          // grp*2*half + pos
            int i1 = i0 + half;
            float sw, cw;
            __sincosf(angstep * (float)pos, &sw, &cw);
            float2 a = s[f*fstride + i0*istride];
            float2 b = s[f*fstride + i1*istride];
            float tx = b.x*cw - b.y*sw;
            float ty = b.x*sw + b.y*cw;
            s[f*fstride + i0*istride] = make_float2(a.x + tx, a.y + ty);
            s[f*fstride + i1*istride] = make_float2(a.x - tx, a.y - ty);
        }
        __syncthreads();
    }
    if (scale != 1.0f) {
        for (int j = tid; j < total; j += nthreads) {
            int f = j % nfft, i = j / nfft;
            float2* p = &s[f*fstride + i*istride];
            p->x *= scale; p->y *= scale;
        }
        __syncthreads();
    }
}

// ---------------- FFT kernels ----------------
// Forward FFT along d (rows), real input -> complex. 4 rows per block.
__global__ void fft_rows_r2c(const float* __restrict__ in, float2* __restrict__ out)
{
    __shared__ float2 s[4*513];
    const int row0 = blockIdx.x * 4;
    const int tid = threadIdx.x;
    for (int j = tid; j < 4*512; j += 256) {
        int r = j >> 9, i = j & 511;
        s[r*513 + i] = make_float2(in[(size_t)(row0 + r)*512 + i], 0.f);
    }
    __syncthreads();
    fftN(s, 512, 9, 4, 513, 1, tid, 256, -1.f, 1.f);
    for (int j = tid; j < 4*512; j += 256) {
        int r = j >> 9, i = j & 511;
        out[(size_t)(row0 + r)*512 + i] = s[r*513 + i];
    }
}

// FFT along c (columns), complex in-place. 8 d-columns per block per batch.
__global__ void fft_cols_c2c(float2* __restrict__ data, float dir, float scale)
{
    __shared__ float2 s[512*9];
    const int b  = blockIdx.y;
    const int d0 = blockIdx.x * 8;
    const int tid = threadIdx.x;
    const size_t base = ((size_t)b * 512) * 512 + d0;
    for (int j = tid; j < 4096; j += 256) {
        int c = j >> 3, dd = j & 7;
        s[dd + c*9] = data[base + (size_t)c*512 + dd];
    }
    __syncthreads();
    fftN(s, 512, 9, 8, /*fstride*/1, /*istride*/9, tid, 256, dir, scale);
    for (int j = tid; j < 4096; j += 256) {
        int c = j >> 3, dd = j & 7;
        data[base + (size_t)c*512 + dd] = s[dd + c*9];
    }
}

// Inverse FFT along d (rows), complex -> abs(float). Writes into cat buffer
// (row stride 1024) at column offset colofs, with extra 1/512 scale (second
// ifft axis normalization).
__global__ void fft_rows_c2abs(const float2* __restrict__ in, float* __restrict__ out)
{
    __shared__ float2 s[4*513];
    const int row0 = blockIdx.x * 4;
    const int tid = threadIdx.x;
    for (int j = tid; j < 4*512; j += 256) {
        int r = j >> 9, i = j & 511;
        s[r*513 + i] = in[(size_t)(row0 + r)*512 + i];
    }
    __syncthreads();
    fftN(s, 512, 9, 4, 513, 1, tid, 256, +1.f, 1.f);
    for (int j = tid; j < 4*512; j += 256) {
        int r = j >> 9, i = j & 511;
        float2 z = s[r*513 + i];
        out[(size_t)(row0 + r)*1024 + i] = sqrtf(z.x*z.x + z.y*z.y) * (1.f/512.f);
    }
}

__global__ void extract_real(const float2* __restrict__ in, float* __restrict__ out)
{
    int i = blockIdx.x * blockDim.x + threadIdx.x;
    if (i < NELEM) out[i] = in[i].x;
}

// ---------------- attention kernel (per (b,c) slice) ----------------
// Includes L2-normalize, complex QK^T, temperature, split softmax, attn@V,
// fused 8x64 2D inverse FFT over (h,w) + abs, writing cat[:, 0:512].
__global__ void __launch_bounds__(256) attention_kernel(
    const float2* __restrict__ qf, const float2* __restrict__ kf,
    const float2* __restrict__ vf, const float* __restrict__ temp,
    float* __restrict__ cat)
{
    const int bc = blockIdx.x;
    const int tid = threadIdx.x;
    __shared__ float2 qs[512], ks[512], vs[512];
    __shared__ float2 attn[64];
    __shared__ float  rq[8], rk[8];

    const size_t base = (size_t)bc * 512;
    for (int j = tid; j < 512; j += 256) {
        qs[j] = qf[base + j];
        ks[j] = kf[base + j];
        vs[j] = vf[base + j];
    }
    __syncthreads();

    // L2 norms per head over w (|z|^2), 8 heads x 32 lanes
    {
        int hd = tid >> 5, ln = tid & 31;
        float2 a;
        float sq = 0.f, sk = 0.f;
        a = qs[hd*64 + ln];      sq += a.x*a.x + a.y*a.y;
        a = qs[hd*64 + ln + 32]; sq += a.x*a.x + a.y*a.y;
        a = ks[hd*64 + ln];      sk += a.x*a.x + a.y*a.y;
        a = ks[hd*64 + ln + 32]; sk += a.x*a.x + a.y*a.y;
        #pragma unroll
        for (int o = 16; o; o >>= 1) {
            sq += __shfl_down_sync(0xffffffffu, sq, o);
            sk += __shfl_down_sync(0xffffffffu, sk, o);
        }
        if (ln == 0) {
            rq[hd] = 1.f / fmaxf(sqrtf(sq), 1e-12f);
            rk[hd] = 1.f / fmaxf(sqrtf(sk), 1e-12f);
        }
    }
    __syncthreads();
    for (int j = tid; j < 512; j += 256) {
        int hd = j >> 6;
        qs[j].x *= rq[hd]; qs[j].y *= rq[hd];
        ks[j].x *= rk[hd]; ks[j].y *= rk[hd];
    }
    __syncthreads();

    // attn[h][g] = temp[h] * sum_w q[h,w]*k[g,w]  (plain complex product)
    {
        int pair = tid >> 2;          // 0..63
        int sub  = tid & 3;
        int h = pair >> 3, g = pair & 7;
        float re = 0.f, im = 0.f;
        for (int w = sub; w < 64; w += 4) {
            float2 a = qs[h*64 + w], b = ks[g*64 + w];
            re += a.x*b.x - a.y*b.y;
            im += a.x*b.y + a.y*b.x;
        }
        re += __shfl_down_sync(0xffffffffu, re, 2);
        im += __shfl_down_sync(0xffffffffu, im, 2);
        re += __shfl_down_sync(0xffffffffu, re, 1);
        im += __shfl_down_sync(0xffffffffu, im, 1);
        if (sub == 0) {
            float t = temp[h];
            attn[pair] = make_float2(re * t, im * t);
        }
    }
    __syncthreads();

    // split softmax over g (real and imag independently)
    if (tid < 8) {
        int h = tid;
        float mr = -1e30f, mi = -1e30f;
        #pragma unroll
        for (int g = 0; g < 8; g++) {
            mr = fmaxf(mr, attn[h*8+g].x);
            mi = fmaxf(mi, attn[h*8+g].y);
        }
        float sr = 0.f, si = 0.f;
        float er[8], ei[8];
        #pragma unroll
        for (int g = 0; g < 8; g++) {
            er[g] = __expf(attn[h*8+g].x - mr); sr += er[g];
            ei[g] = __expf(attn[h*8+g].y - mi); si += ei[g];
        }
        #pragma unroll
        for (int g = 0; g < 8; g++)
            attn[h*8+g] = make_float2(er[g]/sr, ei[g]/si);
    }
    __syncthreads();

    // out[h][w] = sum_g attn[h,g] * v[g,w]  -> reuse qs as output buffer
    for (int j = tid; j < 512; j += 256) {
        int h = j >> 6, w = j & 63;
        float re = 0.f, im = 0.f;
        #pragma unroll
        for (int g = 0; g < 8; g++) {
            float2 a = attn[h*8+g];
            float2 b = vs[g*64 + w];
            re += a.x*b.x - a.y*b.y;
            im += a.x*b.y + a.y*b.x;
        }
        qs[j] = make_float2(re, im);
    }
    __syncthreads();

    // fused ifft2 over (h=8, w=64) + abs, scale 1/512
    fftN(qs, 64, 6, 8,  /*fstride*/64, /*istride*/1,  tid, 256, +1.f, 1.f);
    fftN(qs, 8,  3, 64, /*fstride*/1,  /*istride*/64, tid, 256, +1.f, 1.f);
    for (int j = tid; j < 512; j += 256) {
        float2 z = qs[j];
        cat[(size_t)bc*1024 + j] = sqrtf(z.x*z.x + z.y*z.y) * (1.f/512.f);
    }
}

// ---------------- SGEMM with fused epilogues ----------------
// C[M=16384, N=512] = A[M,K] @ B[K,512] (+ epilogue). 128x128 tile, 256 thr,
// 8x8 per thread, K-chunk 8.
// EPI 0: +bias
// EPI 1: +bias, BatchNorm(channel=row%512) + ReLU   (e0..e3 = mean,var,gamma,beta)
// EPI 2: sigmoid(+bias) * tep (complex) -> cxout
// EPI 3: +bias + add[row*512+col] -> C
template<int EPI>
__global__ void __launch_bounds__(256) sgemm_kernel(
    const float* __restrict__ A, const float* __restrict__ B,
    const float* __restrict__ bias, float* __restrict__ C,
    int K, int lda,
    const float* __restrict__ e0, const float* __restrict__ e1,
    const float* __restrict__ e2, const float* __restrict__ e3,
    const float2* __restrict__ tep, float2* __restrict__ cxout,
    const float* __restrict__ add)
{
    __shared__ float As[8][128];
    __shared__ float Bs[8][128];
    const int tid = threadIdx.x;
    const int tx = tid & 15;   // n
    const int ty = tid >> 4;   // m
    const int rowBase = blockIdx.y * 128;
    const int colBase = blockIdx.x * 128;

    const int arow = tid >> 1, ak = (tid & 1) * 4;
    const int brow = tid >> 5, bcol = (tid & 31) * 4;

    float acc[8][8];
    #pragma unroll
    for (int i = 0; i < 8; i++)
        #pragma unroll
        for (int j = 0; j < 8; j++) acc[i][j] = 0.f;

    for (int k0 = 0; k0 < K; k0 += 8) {
        float4 av = *(const float4*)(A + (size_t)(rowBase + arow)*lda + k0 + ak);
        As[ak+0][arow] = av.x; As[ak+1][arow] = av.y;
        As[ak+2][arow] = av.z; As[ak+3][arow] = av.w;
        float4 bv = *(const float4*)(B + (size_t)(k0 + brow)*512 + colBase + bcol);
        *(float4*)&Bs[brow][bcol] = bv;
        __syncthreads();
        #pragma unroll
        for (int kk = 0; kk < 8; kk++) {
            float af[8], bf[8];
            #pragma unroll
            for (int i = 0; i < 8; i++) af[i] = As[kk][ty*8 + i];
            #pragma unroll
            for (int j = 0; j < 8; j++) bf[j] = Bs[kk][tx*8 + j];
            #pragma unroll
            for (int i = 0; i < 8; i++)
                #pragma unroll
                for (int j = 0; j < 8; j++)
                    acc[i][j] = fmaf(af[i], bf[j], acc[i][j]);
        }
        __syncthreads();
    }

    #pragma unroll
    for (int i = 0; i < 8; i++) {
        const int row = rowBase + ty*8 + i;
        #pragma unroll
        for (int j = 0; j < 8; j++) {
            const int col = colBase + tx*8 + j;
            float val = acc[i][j] + bias[col];
            if (EPI == 0) {
                C[(size_t)row*512 + col] = val;
            } else if (EPI == 1) {
                int ch = row & 511;
                val = (val - e0[ch]) * rsqrtf(e1[ch] + 1e-5f) * e2[ch] + e3[ch];
                C[(size_t)row*512 + col] = fmaxf(val, 0.f);
            } else if (EPI == 2) {
                float sg = 1.f / (1.f + __expf(-val));
                float2 t = tep[(size_t)row*512 + col];
                cxout[(size_t)row*512 + col] = make_float2(sg*t.x, sg*t.y);
            } else { // EPI == 3
                C[(size_t)row*512 + col] = val + add[(size_t)row*512 + col];
            }
        }
    }
}

// ---------------- host launch ----------------
extern "C" void kernel_launch(void* const* d_in, const int* in_sizes, int n_in,
                              void* d_out, int out_size)
{
    const float* x      = (const float*)d_in[0];
    const float* W_in   = (const float*)d_in[1];
    const float* b_in   = (const float*)d_in[2];
    const float* W_q    = (const float*)d_in[3];
    const float* b_q    = (const float*)d_in[4];
    const float* W_k    = (const float*)d_in[5];
    const float* b_k    = (const float*)d_in[6];
    const float* W_v    = (const float*)d_in[7];
    const float* b_v    = (const float*)d_in[8];
    const float* temp   = (const float*)d_in[9];
    const float* W1a    = (const float*)d_in[10];
    const float* b1a    = (const float*)d_in[11];
    const float* bn_g   = (const float*)d_in[12];
    const float* bn_b   = (const float*)d_in[13];
    const float* bn_m   = (const float*)d_in[14];
    const float* bn_v   = (const float*)d_in[15];
    const float* W1b    = (const float*)d_in[16];
    const float* b1b    = (const float*)d_in[17];
    const float* W_out  = (const float*)d_in[18];
    const float* b_out  = (const float*)d_in[19];
    float* out = (float*)d_out;

    float  *conv2, *q, *k, *v, *cat;
    float2 *qf, *kf, *vf, *tep;
    cudaGetSymbolAddress((void**)&conv2, g_conv2);
    cudaGetSymbolAddress((void**)&q,     g_q);
    cudaGetSymbolAddress((void**)&k,     g_k);
    cudaGetSymbolAddress((void**)&v,     g_v);
    cudaGetSymbolAddress((void**)&qf,    g_qf);
    cudaGetSymbolAddress((void**)&kf,    g_kf);
    cudaGetSymbolAddress((void**)&vf,    g_vf);
    cudaGetSymbolAddress((void**)&tep,   g_tep);
    cudaGetSymbolAddress((void**)&cat,   g_cat);

    const dim3 ggrid(4, 128);   // N tiles x M tiles
    const dim3 cgrid(64, 32);   // d-tiles x batch

    // 1) conv2 = x @ W_in + b_in
    sgemm_kernel<0><<<ggrid, 256>>>(x, W_in, b_in, conv2, 512, 512,
                                    nullptr,nullptr,nullptr,nullptr,nullptr,nullptr,nullptr);
    // 2) q,k,v
    sgemm_kernel<0><<<ggrid, 256>>>(conv2, W_q, b_q, q, 512, 512,
                                    nullptr,nullptr,nullptr,nullptr,nullptr,nullptr,nullptr);
    sgemm_kernel<0><<<ggrid, 256>>>(conv2, W_k, b_k, k, 512, 512,
                                    nullptr,nullptr,nullptr,nullptr,nullptr,nullptr,nullptr);
    sgemm_kernel<0><<<ggrid, 256>>>(conv2, W_v, b_v, v, 512, 512,
                                    nullptr,nullptr,nullptr,nullptr,nullptr,nullptr,nullptr);

    // 3) forward fft2 = FFT rows (d) then FFT cols (c)
    fft_rows_r2c<<<4096, 256>>>(q, qf);
    fft_rows_r2c<<<4096, 256>>>(k, kf);
    fft_rows_r2c<<<4096, 256>>>(v, vf);
    fft_rows_r2c<<<4096, 256>>>(conv2, tep);
    fft_cols_c2c<<<cgrid, 256>>>(qf, -1.f, 1.f);
    fft_cols_c2c<<<cgrid, 256>>>(kf, -1.f, 1.f);
    fft_cols_c2c<<<cgrid, 256>>>(vf, -1.f, 1.f);
    fft_cols_c2c<<<cgrid, 256>>>(tep, -1.f, 1.f);

    // 4) attention + fused (h,w) ifft2 + abs -> cat[:, 0:512]
    attention_kernel<<<MM, 256>>>(qf, kf, vf, temp, cat);

    // 5) gated branch: greal = tep.real (reuse q buffer)
    extract_real<<<(NELEM + 255)/256, 256>>>(tep, q);
    // gmid = BN(ReLU-pre) path (reuse k buffer)
    sgemm_kernel<1><<<ggrid, 256>>>(q, W1a, b1a, k, 512, 512,
                                    bn_m, bn_v, bn_g, bn_b, nullptr, nullptr, nullptr);
    // gtep = sigmoid(gmid @ W1b + b1b) * tep  (reuse qf buffer as gtep)
    sgemm_kernel<2><<<ggrid, 256>>>(k, W1b, b1b, nullptr, 512, 512,
                                    nullptr,nullptr,nullptr,nullptr, tep, qf, nullptr);

    // 6) ifft2(gtep) over (c,d) + abs -> cat[:, 512:1024]
    fft_cols_c2c<<<cgrid, 256>>>(qf, +1.f, 1.f/512.f);
    fft_rows_c2abs<<<4096, 256>>>(qf, cat + 512);

    // 7) final: out = cat @ W_out + b_out + conv2
    sgemm_kernel<3><<<ggrid, 256>>>(cat, W_out, b_out, out, 1024, 1024,
                                    nullptr,nullptr,nullptr,nullptr,nullptr,nullptr, conv2);
}

// round 4
// speedup vs baseline: 1.1639x; 1.1639x over previous
#include <cuda_runtime.h>
#include <cuda_bf16.h>
#include <cstdint>

// Problem constants
#define BB 32
#define CC 512
#define DD 512
#define HH 8
#define WW 64
#define MM (BB*CC)          // 16384 rows
#define NELEM (MM*DD)       // 8388608

// ---------------- device scratch (no allocations allowed) ----------------
__device__ float  g_conv2[NELEM];
__device__ float  g_q[NELEM];          // also reused as greal
__device__ float  g_k[NELEM];          // also reused as gmid
__device__ float  g_v[NELEM];
__device__ float2 g_qf[NELEM];         // reused as gtep after attention
__device__ float2 g_kf[NELEM];
__device__ float2 g_vf[NELEM];
__device__ float2 g_tep[NELEM];
__device__ float  g_cat[MM*1024];      // [16384, 1024] concat buffer

// ---------------- small PTX helpers ----------------
__device__ __forceinline__ void cp_async16(void* smem, const void* gmem) {
    uint32_t sa = (uint32_t)__cvta_generic_to_shared(smem);
    asm volatile("cp.async.cg.shared.global [%0], [%1], 16;\n" :: "r"(sa), "l"(gmem));
}
__device__ __forceinline__ void cp_commit() {
    asm volatile("cp.async.commit_group;\n");
}
template<int N> __device__ __forceinline__ void cp_wait() {
    asm volatile("cp.async.wait_group %0;\n" :: "n"(N));
}
__device__ __forceinline__ void mma_tf32(float* d, const uint32_t* a, const uint32_t* b) {
    asm volatile(
        "mma.sync.aligned.m16n8k8.row.col.f32.tf32.tf32.f32 "
        "{%0,%1,%2,%3},{%4,%5,%6,%7},{%8,%9},{%0,%1,%2,%3};\n"
        : "+f"(d[0]), "+f"(d[1]), "+f"(d[2]), "+f"(d[3])
        : "r"(a[0]), "r"(a[1]), "r"(a[2]), "r"(a[3]), "r"(b[0]), "r"(b[1]));
}
__device__ __forceinline__ uint32_t f2tf32(float x) {
    uint32_t r;
    asm("cvt.rna.tf32.f32 %0, %1;" : "=r"(r) : "f"(x));
    return r;
}
// split x into hi (tf32) + lo (tf32 of residual)
__device__ __forceinline__ void tf32_split(float x, uint32_t& hi, uint32_t& lo) {
    hi = f2tf32(x);
    lo = f2tf32(x - __uint_as_float(hi));
}

// ---------------- twiddle table ----------------
// tw[k] = exp(-2*pi*i*k/512), k = 0..255. Works for every power-of-two FFT
// size N <= 512: stage twiddle exp(-i*pi*pos/half) = tw[pos * (256/half)].
__device__ __forceinline__ void build_tw(float2* tw, int tid, int nthreads) {
    for (int k = tid; k < 256; k += nthreads) {
        float s, c;
        __sincosf(-6.28318530717958647692f * (float)k * (1.0f/512.0f), &s, &c);
        tw[k] = make_float2(c, s);
    }
}

// ---------------- generic shared-memory radix-2 FFT (table twiddles) -------
__device__ __forceinline__ void fftN(float2* s, int N, int logN, int nfft,
                                     int fstride, int istride,
                                     int tid, int nthreads,
                                     bool inv, float scale, const float2* tw)
{
    const int total = nfft * N;
    // bit-reverse permutation
    for (int j = tid; j < total; j += nthreads) {
        int f = j % nfft, i = j / nfft;
        int r = (int)(__brev((unsigned)i) >> (32 - logN));
        if (r > i) {
            float2* p0 = &s[f*fstride + i*istride];
            float2* p1 = &s[f*fstride + r*istride];
            float2 t = *p0; *p0 = *p1; *p1 = t;
        }
    }
    __syncthreads();
    for (int half = 1; half < N; half <<= 1) {
        const int nb = nfft * (N >> 1);
        const int tmul = 256 / half;
        for (int j = tid; j < nb; j += nthreads) {
            int f = j % nfft, k = j / nfft;
            int pos = k & (half - 1);
            int i0 = 2*k - pos;
            int i1 = i0 + half;
            float2 t = tw[pos * tmul];
            float cw = t.x;
            float sw = inv ? -t.y : t.y;
            float2 a = s[f*fstride + i0*istride];
            float2 b = s[f*fstride + i1*istride];
            float tx = b.x*cw - b.y*sw;
            float ty = b.x*sw + b.y*cw;
            s[f*fstride + i0*istride] = make_float2(a.x + tx, a.y + ty);
            s[f*fstride + i1*istride] = make_float2(a.x - tx, a.y - ty);
        }
        __syncthreads();
    }
    if (scale != 1.0f) {
        for (int j = tid; j < total; j += nthreads) {
            int f = j % nfft, i = j / nfft;
            float2* p = &s[f*fstride + i*istride];
            p->x *= scale; p->y *= scale;
        }
        __syncthreads();
    }
}

// ---------------- FFT kernels ----------------
__global__ void fft_rows_r2c(const float* __restrict__ in, float2* __restrict__ out)
{
    __shared__ float2 s[4*513];
    __shared__ float2 tw[256];
    const int row0 = blockIdx.x * 4;
    const int tid = threadIdx.x;
    build_tw(tw, tid, 256);
    for (int j = tid; j < 4*512; j += 256) {
        int r = j >> 9, i = j & 511;
        s[r*513 + i] = make_float2(in[(size_t)(row0 + r)*512 + i], 0.f);
    }
    __syncthreads();
    fftN(s, 512, 9, 4, 513, 1, tid, 256, false, 1.f, tw);
    for (int j = tid; j < 4*512; j += 256) {
        int r = j >> 9, i = j & 511;
        out[(size_t)(row0 + r)*512 + i] = s[r*513 + i];
    }
}

__global__ void fft_cols_c2c(float2* __restrict__ data, int inv, float scale)
{
    __shared__ float2 s[512*9];
    __shared__ float2 tw[256];
    const int b  = blockIdx.y;
    const int d0 = blockIdx.x * 8;
    const int tid = threadIdx.x;
    build_tw(tw, tid, 256);
    const size_t base = ((size_t)b * 512) * 512 + d0;
    for (int j = tid; j < 4096; j += 256) {
        int c = j >> 3, dd = j & 7;
        s[dd + c*9] = data[base + (size_t)c*512 + dd];
    }
    __syncthreads();
    fftN(s, 512, 9, 8, /*fstride*/1, /*istride*/9, tid, 256, inv != 0, scale, tw);
    for (int j = tid; j < 4096; j += 256) {
        int c = j >> 3, dd = j & 7;
        data[base + (size_t)c*512 + dd] = s[dd + c*9];
    }
}

__global__ void fft_rows_c2abs(const float2* __restrict__ in, float* __restrict__ out)
{
    __shared__ float2 s[4*513];
    __shared__ float2 tw[256];
    const int row0 = blockIdx.x * 4;
    const int tid = threadIdx.x;
    build_tw(tw, tid, 256);
    for (int j = tid; j < 4*512; j += 256) {
        int r = j >> 9, i = j & 511;
        s[r*513 + i] = in[(size_t)(row0 + r)*512 + i];
    }
    __syncthreads();
    fftN(s, 512, 9, 4, 513, 1, tid, 256, true, 1.f, tw);
    for (int j = tid; j < 4*512; j += 256) {
        int r = j >> 9, i = j & 511;
        float2 z = s[r*513 + i];
        out[(size_t)(row0 + r)*1024 + i] = sqrtf(z.x*z.x + z.y*z.y) * (1.f/512.f);
    }
}

__global__ void extract_real(const float2* __restrict__ in, float* __restrict__ out)
{
    int i = blockIdx.x * blockDim.x + threadIdx.x;
    if (i < NELEM) out[i] = in[i].x;
}

// ---------------- attention kernel (per (b,c) slice) ----------------
__global__ void __launch_bounds__(256) attention_kernel(
    const float2* __restrict__ qf, const float2* __restrict__ kf,
    const float2* __restrict__ vf, const float* __restrict__ temp,
    float* __restrict__ cat)
{
    const int bc = blockIdx.x;
    const int tid = threadIdx.x;
    __shared__ float2 qs[512], ks[512], vs[512];
    __shared__ float2 attn[64];
    __shared__ float  rq[8], rk[8];
    __shared__ float2 tw[256];

    build_tw(tw, tid, 256);
    const size_t base = (size_t)bc * 512;
    for (int j = tid; j < 512; j += 256) {
        qs[j] = qf[base + j];
        ks[j] = kf[base + j];
        vs[j] = vf[base + j];
    }
    __syncthreads();

    // L2 norms per head over w
    {
        int hd = tid >> 5, ln = tid & 31;
        float2 a;
        float sq = 0.f, sk = 0.f;
        a = qs[hd*64 + ln];      sq += a.x*a.x + a.y*a.y;
        a = qs[hd*64 + ln + 32]; sq += a.x*a.x + a.y*a.y;
        a = ks[hd*64 + ln];      sk += a.x*a.x + a.y*a.y;
        a = ks[hd*64 + ln + 32]; sk += a.x*a.x + a.y*a.y;
        #pragma unroll
        for (int o = 16; o; o >>= 1) {
            sq += __shfl_down_sync(0xffffffffu, sq, o);
            sk += __shfl_down_sync(0xffffffffu, sk, o);
        }
        if (ln == 0) {
            rq[hd] = 1.f / fmaxf(sqrtf(sq), 1e-12f);
            rk[hd] = 1.f / fmaxf(sqrtf(sk), 1e-12f);
        }
    }
    __syncthreads();
    for (int j = tid; j < 512; j += 256) {
        int hd = j >> 6;
        qs[j].x *= rq[hd]; qs[j].y *= rq[hd];
        ks[j].x *= rk[hd]; ks[j].y *= rk[hd];
    }
    __syncthreads();

    // attn[h][g] = temp[h] * sum_w q[h,w]*k[g,w]
    {
        int pair = tid >> 2;
        int sub  = tid & 3;
        int h = pair >> 3, g = pair & 7;
        float re = 0.f, im = 0.f;
        for (int w = sub; w < 64; w += 4) {
            float2 a = qs[h*64 + w], b = ks[g*64 + w];
            re += a.x*b.x - a.y*b.y;
            im += a.x*b.y + a.y*b.x;
        }
        re += __shfl_down_sync(0xffffffffu, re, 2);
        im += __shfl_down_sync(0xffffffffu, im, 2);
        re += __shfl_down_sync(0xffffffffu, re, 1);
        im += __shfl_down_sync(0xffffffffu, im, 1);
        if (sub == 0) {
            float t = temp[h];
            attn[pair] = make_float2(re * t, im * t);
        }
    }
    __syncthreads();

    // split softmax over g
    if (tid < 8) {
        int h = tid;
        float mr = -1e30f, mi = -1e30f;
        #pragma unroll
        for (int g = 0; g < 8; g++) {
            mr = fmaxf(mr, attn[h*8+g].x);
            mi = fmaxf(mi, attn[h*8+g].y);
        }
        float sr = 0.f, si = 0.f;
        float er[8], ei[8];
        #pragma unroll
        for (int g = 0; g < 8; g++) {
            er[g] = __expf(attn[h*8+g].x - mr); sr += er[g];
            ei[g] = __expf(attn[h*8+g].y - mi); si += ei[g];
        }
        #pragma unroll
        for (int g = 0; g < 8; g++)
            attn[h*8+g] = make_float2(er[g]/sr, ei[g]/si);
    }
    __syncthreads();

    // out[h][w] = sum_g attn[h,g] * v[g,w]
    for (int j = tid; j < 512; j += 256) {
        int h = j >> 6, w = j & 63;
        float re = 0.f, im = 0.f;
        #pragma unroll
        for (int g = 0; g < 8; g++) {
            float2 a = attn[h*8+g];
            float2 b = vs[g*64 + w];
            re += a.x*b.x - a.y*b.y;
            im += a.x*b.y + a.y*b.x;
        }
        qs[j] = make_float2(re, im);
    }
    __syncthreads();

    // fused ifft2 over (h=8, w=64) + abs, scale 1/512
    fftN(qs, 64, 6, 8,  /*fstride*/64, /*istride*/1,  tid, 256, true, 1.f, tw);
    fftN(qs, 8,  3, 64, /*fstride*/1,  /*istride*/64, tid, 256, true, 1.f, tw);
    for (int j = tid; j < 512; j += 256) {
        float2 z = qs[j];
        cat[(size_t)bc*1024 + j] = sqrtf(z.x*z.x + z.y*z.y) * (1.f/512.f);
    }
}

// ---------------- 3xTF32 tensor-core GEMM with fused epilogues --------------
// C[M=16384, N=512] = A[M,K] @ B[K,512]. 128x128 CTA tile, 256 thr (8 warps,
// 4x2), warp tile 32x64, K-chunk 16, 2-stage cp.async double buffering.
// Each fp32 operand is split hi/lo into tf32; accumulate
// alo*bhi + ahi*blo + ahi*bhi for near-fp32 precision (cuBLAS 3xtf32 scheme).
// EPI 0: +bias
// EPI 1: +bias, BatchNorm(channel=row%512) + ReLU
// EPI 2: sigmoid(+bias) * tep (complex) -> cxout
// EPI 3: +bias + add[row*512+col] -> C
#define BMT 128
#define BNT 128
#define BKT 16
#define AS_LD 20
#define BS_LD 136

template<int EPI>
__global__ void __launch_bounds__(256) mma_gemm(
    const float* __restrict__ A, const float* __restrict__ B,
    const float* __restrict__ bias, float* __restrict__ C,
    int K, int lda,
    const float* __restrict__ e0, const float* __restrict__ e1,
    const float* __restrict__ e2, const float* __restrict__ e3,
    const float2* __restrict__ tep, float2* __restrict__ cxout,
    const float* __restrict__ add)
{
    __shared__ float As[2][BMT*AS_LD];
    __shared__ float Bs[2][BKT*BS_LD];

    const int tid  = threadIdx.x;
    const int lane = tid & 31;
    const int warp = tid >> 5;
    const int gid  = lane >> 2;
    const int tig  = lane & 3;
    const int wr   = warp & 3;     // warp row (0..3)
    const int wc   = warp >> 2;    // warp col (0..1)
    const int rowBase = blockIdx.y * BMT;
    const int colBase = blockIdx.x * BNT;

    // global->smem load indices
    const int ar  = tid >> 2;          // 0..63 (A rows, +64 second half)
    const int akq = (tid & 3) * 4;     // A k offset (float4)
    const int br  = tid >> 5;          // 0..7 (B rows, +8 second half)
    const int bc4 = (tid & 31) * 4;    // B col offset (float4)

    float acc[2][8][4];
    #pragma unroll
    for (int mi = 0; mi < 2; mi++)
        #pragma unroll
        for (int ni = 0; ni < 8; ni++)
            #pragma unroll
            for (int r = 0; r < 4; r++) acc[mi][ni][r] = 0.f;

    const int nt = K / BKT;

    auto prefetch = [&](int kt, int buf) {
        const int k0 = kt * BKT;
        cp_async16(&As[buf][ar*AS_LD + akq],
                   A + (size_t)(rowBase + ar)*lda + k0 + akq);
        cp_async16(&As[buf][(ar + 64)*AS_LD + akq],
                   A + (size_t)(rowBase + ar + 64)*lda + k0 + akq);
        cp_async16(&Bs[buf][br*BS_LD + bc4],
                   B + (size_t)(k0 + br)*512 + colBase + bc4);
        cp_async16(&Bs[buf][(br + 8)*BS_LD + bc4],
                   B + (size_t)(k0 + br + 8)*512 + colBase + bc4);
    };

    prefetch(0, 0);
    cp_commit();

    for (int kt = 0; kt < nt; kt++) {
        if (kt + 1 < nt) {
            prefetch(kt + 1, (kt + 1) & 1);
            cp_commit();
            cp_wait<1>();
        } else {
            cp_wait<0>();
        }
        __syncthreads();

        const float* as = As[kt & 1];
        const float* bs = Bs[kt & 1];

        #pragma unroll
        for (int ks = 0; ks < 2; ks++) {
            const int kb = ks * 8;
            uint32_t ahi[2][4], alo[2][4];
            #pragma unroll
            for (int mi = 0; mi < 2; mi++) {
                const int m = wr*32 + mi*16;
                float f0 = as[(m + gid     )*AS_LD + kb + tig    ];
                float f1 = as[(m + gid + 8 )*AS_LD + kb + tig    ];
                float f2 = as[(m + gid     )*AS_LD + kb + tig + 4];
                float f3 = as[(m + gid + 8 )*AS_LD + kb + tig + 4];
                tf32_split(f0, ahi[mi][0], alo[mi][0]);
                tf32_split(f1, ahi[mi][1], alo[mi][1]);
                tf32_split(f2, ahi[mi][2], alo[mi][2]);
                tf32_split(f3, ahi[mi][3], alo[mi][3]);
            }
            // process n-tiles in two halves of 4 to bound live registers
            #pragma unroll
            for (int nh = 0; nh < 2; nh++) {
                uint32_t bhi[4][2], blo[4][2];
                #pragma unroll
                for (int nj = 0; nj < 4; nj++) {
                    const int n = wc*64 + (nh*4 + nj)*8 + gid;
                    float f0 = bs[(kb + tig    )*BS_LD + n];
                    float f1 = bs[(kb + tig + 4)*BS_LD + n];
                    tf32_split(f0, bhi[nj][0], blo[nj][0]);
                    tf32_split(f1, bhi[nj][1], blo[nj][1]);
                }
                #pragma unroll
                for (int mi = 0; mi < 2; mi++)
                    #pragma unroll
                    for (int nj = 0; nj < 4; nj++) {
                        float* d = acc[mi][nh*4 + nj];
                        mma_tf32(d, alo[mi], bhi[nj]);
                        mma_tf32(d, ahi[mi], blo[nj]);
                        mma_tf32(d, ahi[mi], bhi[nj]);
                    }
            }
        }
        __syncthreads();
    }

    // epilogue
    #pragma unroll
    for (int mi = 0; mi < 2; mi++) {
        #pragma unroll
        for (int ni = 0; ni < 8; ni++) {
            const int col = colBase + wc*64 + ni*8 + 2*tig;
            const float b0 = bias[col], b1 = bias[col + 1];
            #pragma unroll
            for (int half = 0; half < 2; half++) {
                const int row = rowBase + wr*32 + mi*16 + gid + half*8;
                float v0 = acc[mi][ni][half*2 + 0] + b0;
                float v1 = acc[mi][ni][half*2 + 1] + b1;
                if (EPI == 0) {
                    *(float2*)&C[(size_t)row*512 + col] = make_float2(v0, v1);
                } else if (EPI == 1) {
                    const int ch = row & 511;
                    const float sc = rsqrtf(e1[ch] + 1e-5f) * e2[ch];
                    v0 = (v0 - e0[ch]) * sc + e3[ch];
                    v1 = (v1 - e0[ch]) * sc + e3[ch];
                    *(float2*)&C[(size_t)row*512 + col] =
                        make_float2(fmaxf(v0, 0.f), fmaxf(v1, 0.f));
                } else if (EPI == 2) {
                    const float s0 = 1.f / (1.f + __expf(-v0));
                    const float s1 = 1.f / (1.f + __expf(-v1));
                    const float2 t0 = tep[(size_t)row*512 + col];
                    const float2 t1 = tep[(size_t)row*512 + col + 1];
                    cxout[(size_t)row*512 + col]     = make_float2(s0*t0.x, s0*t0.y);
                    cxout[(size_t)row*512 + col + 1] = make_float2(s1*t1.x, s1*t1.y);
                } else { // EPI == 3
                    v0 += add[(size_t)row*512 + col];
                    v1 += add[(size_t)row*512 + col + 1];
                    *(float2*)&C[(size_t)row*512 + col] = make_float2(v0, v1);
                }
            }
        }
    }
}

// ---------------- host launch ----------------
extern "C" void kernel_launch(void* const* d_in, const int* in_sizes, int n_in,
                              void* d_out, int out_size)
{
    const float* x      = (const float*)d_in[0];
    const float* W_in   = (const float*)d_in[1];
    const float* b_in   = (const float*)d_in[2];
    const float* W_q    = (const float*)d_in[3];
    const float* b_q    = (const float*)d_in[4];
    const float* W_k    = (const float*)d_in[5];
    const float* b_k    = (const float*)d_in[6];
    const float* W_v    = (const float*)d_in[7];
    const float* b_v    = (const float*)d_in[8];
    const float* temp   = (const float*)d_in[9];
    const float* W1a    = (const float*)d_in[10];
    const float* b1a    = (const float*)d_in[11];
    const float* bn_g   = (const float*)d_in[12];
    const float* bn_b   = (const float*)d_in[13];
    const float* bn_m   = (const float*)d_in[14];
    const float* bn_v   = (const float*)d_in[15];
    const float* W1b    = (const float*)d_in[16];
    const float* b1b    = (const float*)d_in[17];
    const float* W_out  = (const float*)d_in[18];
    const float* b_out  = (const float*)d_in[19];
    float* out = (float*)d_out;

    float  *conv2, *q, *k, *v, *cat;
    float2 *qf, *kf, *vf, *tep;
    cudaGetSymbolAddress((void**)&conv2, g_conv2);
    cudaGetSymbolAddress((void**)&q,     g_q);
    cudaGetSymbolAddress((void**)&k,     g_k);
    cudaGetSymbolAddress((void**)&v,     g_v);
    cudaGetSymbolAddress((void**)&qf,    g_qf);
    cudaGetSymbolAddress((void**)&kf,    g_kf);
    cudaGetSymbolAddress((void**)&vf,    g_vf);
    cudaGetSymbolAddress((void**)&tep,   g_tep);
    cudaGetSymbolAddress((void**)&cat,   g_cat);

    const dim3 ggrid(4, 128);   // N tiles x M tiles
    const dim3 cgrid(64, 32);   // d-tiles x batch

    // 1) conv2 = x @ W_in + b_in
    mma_gemm<0><<<ggrid, 256>>>(x, W_in, b_in, conv2, 512, 512,
                                nullptr,nullptr,nullptr,nullptr,nullptr,nullptr,nullptr);
    // 2) q,k,v
    mma_gemm<0><<<ggrid, 256>>>(conv2, W_q, b_q, q, 512, 512,
                                nullptr,nullptr,nullptr,nullptr,nullptr,nullptr,nullptr);
    mma_gemm<0><<<ggrid, 256>>>(conv2, W_k, b_k, k, 512, 512,
                                nullptr,nullptr,nullptr,nullptr,nullptr,nullptr,nullptr);
    mma_gemm<0><<<ggrid, 256>>>(conv2, W_v, b_v, v, 512, 512,
                                nullptr,nullptr,nullptr,nullptr,nullptr,nullptr,nullptr);

    // 3) forward fft2 = FFT rows (d) then FFT cols (c)
    fft_rows_r2c<<<4096, 256>>>(q, qf);
    fft_rows_r2c<<<4096, 256>>>(k, kf);
    fft_rows_r2c<<<4096, 256>>>(v, vf);
    fft_rows_r2c<<<4096, 256>>>(conv2, tep);
    fft_cols_c2c<<<cgrid, 256>>>(qf, 0, 1.f);
    fft_cols_c2c<<<cgrid, 256>>>(kf, 0, 1.f);
    fft_cols_c2c<<<cgrid, 256>>>(vf, 0, 1.f);
    fft_cols_c2c<<<cgrid, 256>>>(tep, 0, 1.f);

    // 4) attention + fused (h,w) ifft2 + abs -> cat[:, 0:512]
    attention_kernel<<<MM, 256>>>(qf, kf, vf, temp, cat);

    // 5) gated branch
    extract_real<<<(NELEM + 255)/256, 256>>>(tep, q);
    mma_gemm<1><<<ggrid, 256>>>(q, W1a, b1a, k, 512, 512,
                                bn_m, bn_v, bn_g, bn_b, nullptr, nullptr, nullptr);
    mma_gemm<2><<<ggrid, 256>>>(k, W1b, b1b, nullptr, 512, 512,
                                nullptr,nullptr,nullptr,nullptr, tep, qf, nullptr);

    // 6) ifft2(gtep) over (c,d) + abs -> cat[:, 512:1024]
    fft_cols_c2c<<<cgrid, 256>>>(qf, 1, 1.f/512.f);
    fft_rows_c2abs<<<4096, 256>>>(qf, cat + 512);

    // 7) final: out = cat @ W_out + b_out + conv2
    mma_gemm<3><<<ggrid, 256>>>(cat, W_out, b_out, out, 1024, 1024,
                                nullptr,nullptr,nullptr,nullptr,nullptr,nullptr, conv2);
}

// round 5
// speedup vs baseline: 1.8200x; 1.5637x over previous
#include <cuda_runtime.h>
#include <cuda_bf16.h>
#include <cstdint>
#include <math.h>

// Problem constants
#define BB 32
#define CC 512
#define DD 512
#define HH 8
#define WW 64
#define MM (BB*CC)          // 16384 rows
#define NELEM (MM*DD)       // 8388608

// ---------------- device scratch (no allocations allowed) ----------------
__device__ float  g_conv2[NELEM];
__device__ float  g_q[NELEM];          // also reused as greal
__device__ float  g_k[NELEM];          // also reused as gmid
__device__ float  g_v[NELEM];
__device__ float2 g_qf[NELEM];         // reused as gtep after attention
__device__ float2 g_kf[NELEM];
__device__ float2 g_vf[NELEM];
__device__ float2 g_tep[NELEM];
__device__ float  g_cat[MM*1024];      // [16384, 1024] concat buffer
__device__ float2 g_tw512[512];        // exp(-2*pi*i*k/512)

// ---------------- small PTX helpers ----------------
__device__ __forceinline__ void cp_async16(void* smem, const void* gmem) {
    uint32_t sa = (uint32_t)__cvta_generic_to_shared(smem);
    asm volatile("cp.async.cg.shared.global [%0], [%1], 16;\n" :: "r"(sa), "l"(gmem));
}
__device__ __forceinline__ void cp_commit() {
    asm volatile("cp.async.commit_group;\n");
}
template<int N> __device__ __forceinline__ void cp_wait() {
    asm volatile("cp.async.wait_group %0;\n" :: "n"(N));
}
__device__ __forceinline__ void mma_tf32(float* d, const uint32_t* a, const uint32_t* b) {
    asm volatile(
        "mma.sync.aligned.m16n8k8.row.col.f32.tf32.tf32.f32 "
        "{%0,%1,%2,%3},{%4,%5,%6,%7},{%8,%9},{%0,%1,%2,%3};\n"
        : "+f"(d[0]), "+f"(d[1]), "+f"(d[2]), "+f"(d[3])
        : "r"(a[0]), "r"(a[1]), "r"(a[2]), "r"(a[3]), "r"(b[0]), "r"(b[1]));
}
__device__ __forceinline__ uint32_t f2tf32(float x) {
    uint32_t r;
    asm("cvt.rna.tf32.f32 %0, %1;" : "=r"(r) : "f"(x));
    return r;
}
__device__ __forceinline__ void tf32_split(float x, uint32_t& hi, uint32_t& lo) {
    hi = f2tf32(x);
    lo = f2tf32(x - __uint_as_float(hi));
}

// ---------------- complex helpers + radix-8 butterfly ----------------
__device__ __forceinline__ float2 cadd(float2 a, float2 b) { return make_float2(a.x+b.x, a.y+b.y); }
__device__ __forceinline__ float2 csub(float2 a, float2 b) { return make_float2(a.x-b.x, a.y-b.y); }
__device__ __forceinline__ float2 cmul(float2 a, float2 b) {
    return make_float2(a.x*b.x - a.y*b.y, a.x*b.y + a.y*b.x);
}
// forward 8-point DFT, in place, natural order output: y[k] = sum_a x[a] W8^{ak}
__device__ __forceinline__ void fft8(float2* x)
{
    const float cc = 0.70710678118654752440f;
    float2 u0 = cadd(x[0], x[4]), u1 = cadd(x[1], x[5]);
    float2 u2 = cadd(x[2], x[6]), u3 = cadd(x[3], x[7]);
    float2 v0 = csub(x[0], x[4]), v1 = csub(x[1], x[5]);
    float2 v2 = csub(x[2], x[6]), v3 = csub(x[3], x[7]);
    float2 a0 = cadd(u0, u2), a1 = cadd(u1, u3);
    float2 b0 = csub(u0, u2), b1 = csub(u1, u3);
    float2 w1 = make_float2(cc*(v1.x + v1.y), cc*(v1.y - v1.x));     // W8^1 * v1
    float2 w2 = make_float2(v2.y, -v2.x);                            // -i * v2
    float2 w3 = make_float2(cc*(v3.y - v3.x), -cc*(v3.x + v3.y));    // W8^3 * v3
    float2 A0 = cadd(v0, w2), A1 = cadd(w1, w3);
    float2 B0 = csub(v0, w2), B1 = csub(w1, w3);
    x[0] = cadd(a0, a1);
    x[1] = cadd(A0, A1);
    x[2] = make_float2(b0.x + b1.y, b0.y - b1.x);   // b0 - i b1
    x[3] = make_float2(B0.x + B1.y, B0.y - B1.x);
    x[4] = csub(a0, a1);
    x[5] = csub(A0, A1);
    x[6] = make_float2(b0.x - b1.y, b0.y + b1.x);   // b0 + i b1
    x[7] = make_float2(B0.x - B1.y, B0.y + B1.x);
}

// 512-pt forward FFT, 8 interleaved FFTs per block (512 threads).
// Element i of this FFT lives at s9[i*9] (pad-9 float2 layout).
// j = thread's group index 0..63. Output in NATURAL order.
__device__ __forceinline__ void fft512_core(float2* s9, const float2* tw, int j)
{
    float2 x[8];
    // stage 0: stride 64, twiddle W512^{j*s}
    #pragma unroll
    for (int a = 0; a < 8; a++) x[a] = s9[(j + 64*a)*9];
    fft8(x);
    #pragma unroll
    for (int s = 1; s < 8; s++) x[s] = cmul(x[s], tw[j*s]);
    #pragma unroll
    for (int s = 0; s < 8; s++) s9[(j + 64*s)*9] = x[s];
    __syncthreads();
    // stage 1: within 64-blocks, stride 8, twiddle W64^{j1*s} = tw[8*j1*s]
    const int b = j >> 3, j1 = j & 7;
    const int base = b * 64;
    #pragma unroll
    for (int a = 0; a < 8; a++) x[a] = s9[(base + j1 + 8*a)*9];
    fft8(x);
    #pragma unroll
    for (int s = 1; s < 8; s++) x[s] = cmul(x[s], tw[(j1*s)*8]);
    #pragma unroll
    for (int s = 0; s < 8; s++) s9[(base + j1 + 8*s)*9] = x[s];
    __syncthreads();
    // stage 2: contiguous 8-blocks, store digit-reversed -> natural order
    #pragma unroll
    for (int a = 0; a < 8; a++) x[a] = s9[(8*j + a)*9];
    __syncthreads();                 // writes below cross thread read sets
    fft8(x);
    const int ob = 8*(j & 7) + (j >> 3);
    #pragma unroll
    for (int s = 0; s < 8; s++) s9[(64*s + ob)*9] = x[s];
    __syncthreads();
}

// ---------------- twiddle init (once per launch, graph-capturable) --------
__global__ void init_tw512()
{
    int k = threadIdx.x;
    double ang = -6.283185307179586476925286766559 * (double)k / 512.0;
    double s, c;
    sincos(ang, &s, &c);
    g_tw512[k] = make_float2((float)c, (float)s);
}

// ---------------- FFT kernels (8 FFTs of 512 per block, 512 threads) ------
__global__ void __launch_bounds__(512) fft512_rows_r2c8(
    const float* __restrict__ in, float2* __restrict__ out)
{
    __shared__ float2 s[512*9];
    __shared__ float2 tw[512];
    const int tid = threadIdx.x;
    tw[tid] = g_tw512[tid];
    const int row0 = blockIdx.x * 8;
    for (int idx = tid; idx < 4096; idx += 512) {
        int f = idx >> 9, i = idx & 511;
        s[i*9 + f] = make_float2(in[(size_t)(row0 + f)*512 + i], 0.f);
    }
    __syncthreads();
    fft512_core(s + (tid & 7), tw, tid >> 3);
    for (int idx = tid; idx < 4096; idx += 512) {
        int f = idx >> 9, k = idx & 511;
        out[(size_t)(row0 + f)*512 + k] = s[k*9 + f];
    }
}

__global__ void __launch_bounds__(512) fft512_cols8(
    float2* __restrict__ data, int inv, float scale)
{
    __shared__ float2 s[512*9];
    __shared__ float2 tw[512];
    const int tid = threadIdx.x;
    tw[tid] = g_tw512[tid];
    const size_t base = ((size_t)blockIdx.y * 512) * 512 + blockIdx.x * 8;
    for (int idx = tid; idx < 4096; idx += 512) {
        int c = idx >> 3, dd = idx & 7;
        float2 v = data[base + (size_t)c*512 + dd];
        if (inv) v.y = -v.y;
        s[c*9 + dd] = v;
    }
    __syncthreads();
    fft512_core(s + (tid & 7), tw, tid >> 3);
    for (int idx = tid; idx < 4096; idx += 512) {
        int c = idx >> 3, dd = idx & 7;
        float2 v = s[c*9 + dd];
        if (inv) v.y = -v.y;
        v.x *= scale; v.y *= scale;
        data[base + (size_t)c*512 + dd] = v;
    }
}

// inverse along rows + abs -> cat buffer (row stride 1024), extra 1/512
__global__ void __launch_bounds__(512) fft512_rows_c2abs8(
    const float2* __restrict__ in, float* __restrict__ out)
{
    __shared__ float2 s[512*9];
    __shared__ float2 tw[512];
    const int tid = threadIdx.x;
    tw[tid] = g_tw512[tid];
    const int row0 = blockIdx.x * 8;
    for (int idx = tid; idx < 4096; idx += 512) {
        int f = idx >> 9, i = idx & 511;
        float2 v = in[(size_t)(row0 + f)*512 + i];
        v.y = -v.y;                                 // conj for inverse
        s[i*9 + f] = v;
    }
    __syncthreads();
    fft512_core(s + (tid & 7), tw, tid >> 3);
    for (int idx = tid; idx < 4096; idx += 512) {
        int f = idx >> 9, k = idx & 511;
        float2 z = s[k*9 + f];
        out[(size_t)(row0 + f)*1024 + k] = sqrtf(z.x*z.x + z.y*z.y) * (1.f/512.f);
    }
}

__global__ void extract_real(const float2* __restrict__ in, float* __restrict__ out)
{
    int i = blockIdx.x * blockDim.x + threadIdx.x;
    if (i < NELEM) out[i] = in[i].x;
}

// ---------------- attention kernel (per (b,c) slice) ----------------
__global__ void __launch_bounds__(256) attention_kernel(
    const float2* __restrict__ qf, const float2* __restrict__ kf,
    const float2* __restrict__ vf, const float* __restrict__ temp,
    float* __restrict__ cat)
{
    const int bc = blockIdx.x;
    const int tid = threadIdx.x;
    __shared__ float2 qs[512], ks[512], vs[512];
    __shared__ float2 attn[64];
    __shared__ float  rq[8], rk[8];
    __shared__ float2 tw[512];

    tw[tid]       = g_tw512[tid];
    tw[tid + 256] = g_tw512[tid + 256];
    const size_t base = (size_t)bc * 512;
    for (int j = tid; j < 512; j += 256) {
        qs[j] = qf[base + j];
        ks[j] = kf[base + j];
        vs[j] = vf[base + j];
    }
    __syncthreads();

    // L2 norms per head over w
    {
        int hd = tid >> 5, ln = tid & 31;
        float2 a;
        float sq = 0.f, sk = 0.f;
        a = qs[hd*64 + ln];      sq += a.x*a.x + a.y*a.y;
        a = qs[hd*64 + ln + 32]; sq += a.x*a.x + a.y*a.y;
        a = ks[hd*64 + ln];      sk += a.x*a.x + a.y*a.y;
        a = ks[hd*64 + ln + 32]; sk += a.x*a.x + a.y*a.y;
        #pragma unroll
        for (int o = 16; o; o >>= 1) {
            sq += __shfl_down_sync(0xffffffffu, sq, o);
            sk += __shfl_down_sync(0xffffffffu, sk, o);
        }
        if (ln == 0) {
            rq[hd] = 1.f / fmaxf(sqrtf(sq), 1e-12f);
            rk[hd] = 1.f / fmaxf(sqrtf(sk), 1e-12f);
        }
    }
    __syncthreads();
    for (int j = tid; j < 512; j += 256) {
        int hd = j >> 6;
        qs[j].x *= rq[hd]; qs[j].y *= rq[hd];
        ks[j].x *= rk[hd]; ks[j].y *= rk[hd];
    }
    __syncthreads();

    // attn[h][g] = temp[h] * sum_w q[h,w]*k[g,w]
    {
        int pair = tid >> 2;
        int sub  = tid & 3;
        int h = pair >> 3, g = pair & 7;
        float re = 0.f, im = 0.f;
        for (int w = sub; w < 64; w += 4) {
            float2 a = qs[h*64 + w], b = ks[g*64 + w];
            re += a.x*b.x - a.y*b.y;
            im += a.x*b.y + a.y*b.x;
        }
        re += __shfl_down_sync(0xffffffffu, re, 2);
        im += __shfl_down_sync(0xffffffffu, im, 2);
        re += __shfl_down_sync(0xffffffffu, re, 1);
        im += __shfl_down_sync(0xffffffffu, im, 1);
        if (sub == 0) {
            float t = temp[h];
            attn[pair] = make_float2(re * t, im * t);
        }
    }
    __syncthreads();

    // split softmax over g
    if (tid < 8) {
        int h = tid;
        float mr = -1e30f, mi = -1e30f;
        #pragma unroll
        for (int g = 0; g < 8; g++) {
            mr = fmaxf(mr, attn[h*8+g].x);
            mi = fmaxf(mi, attn[h*8+g].y);
        }
        float sr = 0.f, si = 0.f;
        float er[8], ei[8];
        #pragma unroll
        for (int g = 0; g < 8; g++) {
            er[g] = __expf(attn[h*8+g].x - mr); sr += er[g];
            ei[g] = __expf(attn[h*8+g].y - mi); si += ei[g];
        }
        #pragma unroll
        for (int g = 0; g < 8; g++)
            attn[h*8+g] = make_float2(er[g]/sr, ei[g]/si);
    }
    __syncthreads();

    // out[h][w] = sum_g attn[h,g] * v[g,w]; store CONJUGATED (ifft via conj)
    for (int j = tid; j < 512; j += 256) {
        int h = j >> 6, w = j & 63;
        float re = 0.f, im = 0.f;
        #pragma unroll
        for (int g = 0; g < 8; g++) {
            float2 a = attn[h*8+g];
            float2 b = vs[g*64 + w];
            re += a.x*b.x - a.y*b.y;
            im += a.x*b.y + a.y*b.x;
        }
        qs[j] = make_float2(re, -im);
    }
    __syncthreads();

    // fft2 over (h=8, w=64) of conj -> |.| = |ifft2| * 512
    // w-axis: 64-pt radix-8, 2 stages, threads 0..63 (fh = t>>3, j1 = t&7)
    {
        const bool act = tid < 64;
        const int fh = tid >> 3, j1 = tid & 7;
        float2 x[8];
        if (act) {
            #pragma unroll
            for (int a = 0; a < 8; a++) x[a] = qs[fh*64 + j1 + 8*a];
            fft8(x);
            #pragma unroll
            for (int s = 1; s < 8; s++) x[s] = cmul(x[s], tw[(j1*s)*8]);
            #pragma unroll
            for (int s = 0; s < 8; s++) qs[fh*64 + j1 + 8*s] = x[s];
        }
        __syncthreads();
        if (act) {
            #pragma unroll
            for (int a = 0; a < 8; a++) x[a] = qs[fh*64 + 8*j1 + a];
        }
        __syncthreads();
        if (act) {
            fft8(x);
            #pragma unroll
            for (int m = 0; m < 8; m++) qs[fh*64 + 8*m + j1] = x[m];
        }
        __syncthreads();
        // h-axis: 8-pt, one stage, thread w = tid (0..63), column private
        if (act) {
            const int w = tid;
            #pragma unroll
            for (int a = 0; a < 8; a++) x[a] = qs[a*64 + w];
            fft8(x);
            #pragma unroll
            for (int s = 0; s < 8; s++) qs[s*64 + w] = x[s];
        }
        __syncthreads();
    }
    for (int j = tid; j < 512; j += 256) {
        float2 z = qs[j];
        cat[(size_t)bc*1024 + j] = sqrtf(z.x*z.x + z.y*z.y) * (1.f/512.f);
    }
}

// ---------------- 3xTF32 tensor-core GEMM with fused epilogues --------------
#define BMT 128
#define BNT 128
#define BKT 16
#define AS_LD 20
#define BS_LD 136

template<int EPI>
__device__ __forceinline__ void gemm_body(
    const float* __restrict__ A, const float* __restrict__ B,
    const float* __restrict__ bias, float* __restrict__ C,
    int K, int lda,
    const float* __restrict__ e0, const float* __restrict__ e1,
    const float* __restrict__ e2, const float* __restrict__ e3,
    const float2* __restrict__ tep, float2* __restrict__ cxout,
    const float* __restrict__ add)
{
    __shared__ float As[2][BMT*AS_LD];
    __shared__ float Bs[2][BKT*BS_LD];

    const int tid  = threadIdx.x;
    const int lane = tid & 31;
    const int warp = tid >> 5;
    const int gid  = lane >> 2;
    const int tig  = lane & 3;
    const int wr   = warp & 3;
    const int wc   = warp >> 2;
    const int rowBase = blockIdx.y * BMT;
    const int colBase = blockIdx.x * BNT;

    const int ar  = tid >> 2;
    const int akq = (tid & 3) * 4;
    const int br  = tid >> 5;
    const int bc4 = (tid & 31) * 4;

    float acc[2][8][4];
    #pragma unroll
    for (int mi = 0; mi < 2; mi++)
        #pragma unroll
        for (int ni = 0; ni < 8; ni++)
            #pragma unroll
            for (int r = 0; r < 4; r++) acc[mi][ni][r] = 0.f;

    const int nt = K / BKT;

    auto prefetch = [&](int kt, int buf) {
        const int k0 = kt * BKT;
        cp_async16(&As[buf][ar*AS_LD + akq],
                   A + (size_t)(rowBase + ar)*lda + k0 + akq);
        cp_async16(&As[buf][(ar + 64)*AS_LD + akq],
                   A + (size_t)(rowBase + ar + 64)*lda + k0 + akq);
        cp_async16(&Bs[buf][br*BS_LD + bc4],
                   B + (size_t)(k0 + br)*512 + colBase + bc4);
        cp_async16(&Bs[buf][(br + 8)*BS_LD + bc4],
                   B + (size_t)(k0 + br + 8)*512 + colBase + bc4);
    };

    prefetch(0, 0);
    cp_commit();

    for (int kt = 0; kt < nt; kt++) {
        if (kt + 1 < nt) {
            prefetch(kt + 1, (kt + 1) & 1);
            cp_commit();
            cp_wait<1>();
        } else {
            cp_wait<0>();
        }
        __syncthreads();

        const float* as = As[kt & 1];
        const float* bs = Bs[kt & 1];

        #pragma unroll
        for (int ks = 0; ks < 2; ks++) {
            const int kb = ks * 8;
            uint32_t ahi[2][4], alo[2][4];
            #pragma unroll
            for (int mi = 0; mi < 2; mi++) {
                const int m = wr*32 + mi*16;
                float f0 = as[(m + gid     )*AS_LD + kb + tig    ];
                float f1 = as[(m + gid + 8 )*AS_LD + kb + tig    ];
                float f2 = as[(m + gid     )*AS_LD + kb + tig + 4];
                float f3 = as[(m + gid + 8 )*AS_LD + kb + tig + 4];
                tf32_split(f0, ahi[mi][0], alo[mi][0]);
                tf32_split(f1, ahi[mi][1], alo[mi][1]);
                tf32_split(f2, ahi[mi][2], alo[mi][2]);
                tf32_split(f3, ahi[mi][3], alo[mi][3]);
            }
            #pragma unroll
            for (int nh = 0; nh < 2; nh++) {
                uint32_t bhi[4][2], blo[4][2];
                #pragma unroll
                for (int nj = 0; nj < 4; nj++) {
                    const int n = wc*64 + (nh*4 + nj)*8 + gid;
                    float f0 = bs[(kb + tig    )*BS_LD + n];
                    float f1 = bs[(kb + tig + 4)*BS_LD + n];
                    tf32_split(f0, bhi[nj][0], blo[nj][0]);
                    tf32_split(f1, bhi[nj][1], blo[nj][1]);
                }
                #pragma unroll
                for (int mi = 0; mi < 2; mi++)
                    #pragma unroll
                    for (int nj = 0; nj < 4; nj++) {
                        float* d = acc[mi][nh*4 + nj];
                        mma_tf32(d, alo[mi], bhi[nj]);
                        mma_tf32(d, ahi[mi], blo[nj]);
                        mma_tf32(d, ahi[mi], bhi[nj]);
                    }
            }
        }
        __syncthreads();
    }

    #pragma unroll
    for (int mi = 0; mi < 2; mi++) {
        #pragma unroll
        for (int ni = 0; ni < 8; ni++) {
            const int col = colBase + wc*64 + ni*8 + 2*tig;
            const float b0 = bias[col], b1 = bias[col + 1];
            #pragma unroll
            for (int half = 0; half < 2; half++) {
                const int row = rowBase + wr*32 + mi*16 + gid + half*8;
                float v0 = acc[mi][ni][half*2 + 0] + b0;
                float v1 = acc[mi][ni][half*2 + 1] + b1;
                if (EPI == 0) {
                    *(float2*)&C[(size_t)row*512 + col] = make_float2(v0, v1);
                } else if (EPI == 1) {
                    const int ch = row & 511;
                    const float sc = rsqrtf(e1[ch] + 1e-5f) * e2[ch];
                    v0 = (v0 - e0[ch]) * sc + e3[ch];
                    v1 = (v1 - e0[ch]) * sc + e3[ch];
                    *(float2*)&C[(size_t)row*512 + col] =
                        make_float2(fmaxf(v0, 0.f), fmaxf(v1, 0.f));
                } else if (EPI == 2) {
                    const float s0 = 1.f / (1.f + __expf(-v0));
                    const float s1 = 1.f / (1.f + __expf(-v1));
                    const float2 t0 = tep[(size_t)row*512 + col];
                    const float2 t1 = tep[(size_t)row*512 + col + 1];
                    cxout[(size_t)row*512 + col]     = make_float2(s0*t0.x, s0*t0.y);
                    cxout[(size_t)row*512 + col + 1] = make_float2(s1*t1.x, s1*t1.y);
                } else { // EPI == 3
                    v0 += add[(size_t)row*512 + col];
                    v1 += add[(size_t)row*512 + col + 1];
                    *(float2*)&C[(size_t)row*512 + col] = make_float2(v0, v1);
                }
            }
        }
    }
}

template<int EPI>
__global__ void __launch_bounds__(256) mma_gemm(
    const float* __restrict__ A, const float* __restrict__ B,
    const float* __restrict__ bias, float* __restrict__ C,
    int K, int lda,
    const float* __restrict__ e0, const float* __restrict__ e1,
    const float* __restrict__ e2, const float* __restrict__ e3,
    const float2* __restrict__ tep, float2* __restrict__ cxout,
    const float* __restrict__ add)
{
    gemm_body<EPI>(A, B, bias, C, K, lda, e0, e1, e2, e3, tep, cxout, add);
}

// fused q/k/v: blockIdx.z selects weight/bias/output set
__global__ void __launch_bounds__(256) mma_gemm_qkv(
    const float* __restrict__ A,
    const float* __restrict__ B0, const float* __restrict__ bi0, float* __restrict__ C0,
    const float* __restrict__ B1, const float* __restrict__ bi1, float* __restrict__ C1,
    const float* __restrict__ B2, const float* __restrict__ bi2, float* __restrict__ C2)
{
    const int z = blockIdx.z;
    const float* B    = (z == 0) ? B0  : (z == 1) ? B1  : B2;
    const float* bias = (z == 0) ? bi0 : (z == 1) ? bi1 : bi2;
    float*       C    = (z == 0) ? C0  : (z == 1) ? C1  : C2;
    gemm_body<0>(A, B, bias, C, 512, 512,
                 nullptr, nullptr, nullptr, nullptr, nullptr, nullptr, nullptr);
}

// ---------------- host launch ----------------
extern "C" void kernel_launch(void* const* d_in, const int* in_sizes, int n_in,
                              void* d_out, int out_size)
{
    const float* x      = (const float*)d_in[0];
    const float* W_in   = (const float*)d_in[1];
    const float* b_in   = (const float*)d_in[2];
    const float* W_q    = (const float*)d_in[3];
    const float* b_q    = (const float*)d_in[4];
    const float* W_k    = (const float*)d_in[5];
    const float* b_k    = (const float*)d_in[6];
    const float* W_v    = (const float*)d_in[7];
    const float* b_v    = (const float*)d_in[8];
    const float* temp   = (const float*)d_in[9];
    const float* W1a    = (const float*)d_in[10];
    const float* b1a    = (const float*)d_in[11];
    const float* bn_g   = (const float*)d_in[12];
    const float* bn_b   = (const float*)d_in[13];
    const float* bn_m   = (const float*)d_in[14];
    const float* bn_v   = (const float*)d_in[15];
    const float* W1b    = (const float*)d_in[16];
    const float* b1b    = (const float*)d_in[17];
    const float* W_out  = (const float*)d_in[18];
    const float* b_out  = (const float*)d_in[19];
    float* out = (float*)d_out;

    float  *conv2, *q, *k, *v, *cat;
    float2 *qf, *kf, *vf, *tep;
    cudaGetSymbolAddress((void**)&conv2, g_conv2);
    cudaGetSymbolAddress((void**)&q,     g_q);
    cudaGetSymbolAddress((void**)&k,     g_k);
    cudaGetSymbolAddress((void**)&v,     g_v);
    cudaGetSymbolAddress((void**)&qf,    g_qf);
    cudaGetSymbolAddress((void**)&kf,    g_kf);
    cudaGetSymbolAddress((void**)&vf,    g_vf);
    cudaGetSymbolAddress((void**)&tep,   g_tep);
    cudaGetSymbolAddress((void**)&cat,   g_cat);

    const dim3 ggrid(4, 128);       // N tiles x M tiles
    const dim3 qgrid(4, 128, 3);    // + qkv
    const dim3 cgrid(64, 32);       // d-tiles x batch
    const int  rgrid = MM / 8;      // 2048 row-FFT blocks

    init_tw512<<<1, 512>>>();

    // 1) conv2 = x @ W_in + b_in
    mma_gemm<0><<<ggrid, 256>>>(x, W_in, b_in, conv2, 512, 512,
                                nullptr,nullptr,nullptr,nullptr,nullptr,nullptr,nullptr);
    // 2) q,k,v fused
    mma_gemm_qkv<<<qgrid, 256>>>(conv2, W_q, b_q, q, W_k, b_k, k, W_v, b_v, v);

    // 3) forward fft2 = FFT rows (d) then FFT cols (c)
    fft512_rows_r2c8<<<rgrid, 512>>>(q, qf);
    fft512_rows_r2c8<<<rgrid, 512>>>(k, kf);
    fft512_rows_r2c8<<<rgrid, 512>>>(v, vf);
    fft512_rows_r2c8<<<rgrid, 512>>>(conv2, tep);
    fft512_cols8<<<cgrid, 512>>>(qf, 0, 1.f);
    fft512_cols8<<<cgrid, 512>>>(kf, 0, 1.f);
    fft512_cols8<<<cgrid, 512>>>(vf, 0, 1.f);
    fft512_cols8<<<cgrid, 512>>>(tep, 0, 1.f);

    // 4) attention + fused (h,w) ifft2 + abs -> cat[:, 0:512]
    attention_kernel<<<MM, 256>>>(qf, kf, vf, temp, cat);

    // 5) gated branch
    extract_real<<<(NELEM + 255)/256, 256>>>(tep, q);
    mma_gemm<1><<<ggrid, 256>>>(q, W1a, b1a, k, 512, 512,
                                bn_m, bn_v, bn_g, bn_b, nullptr, nullptr, nullptr);
    mma_gemm<2><<<ggrid, 256>>>(k, W1b, b1b, nullptr, 512, 512,
                                nullptr,nullptr,nullptr,nullptr, tep, qf, nullptr);

    // 6) ifft2(gtep) over (c,d) + abs -> cat[:, 512:1024]
    fft512_cols8<<<cgrid, 512>>>(qf, 1, 1.f/512.f);
    fft512_rows_c2abs8<<<rgrid, 512>>>(qf, cat + 512);

    // 7) final: out = cat @ W_out + b_out + conv2
    mma_gemm<3><<<ggrid, 256>>>(cat, W_out, b_out, out, 1024, 1024,
                                nullptr,nullptr,nullptr,nullptr,nullptr,nullptr, conv2);
}